// round 3
// baseline (speedup 1.0000x reference)
#include <cuda_runtime.h>
#include <math.h>

// Problem constants
#define BATCH 4
#define HW 16384          // 128*128
#define HH 128
#define WW 128
#define OFFC 18           // 2*K
#define KK 9
#define CMID 128
#define EPS 1e-5f

typedef unsigned long long ull;

__device__ __forceinline__ void fma2(ull &d, ull a, ull b) {
    asm("fma.rn.f32x2 %0, %1, %2, %0;" : "+l"(d) : "l"(a), "l"(b));
}

// -------- scratch (device globals; no allocation) --------
__device__ float g_off[BATCH * OFFC * HW];          // offset maps
__device__ float g_t1 [BATCH * CMID * HW];          // stage1 activations
__device__ float g_t2 [BATCH * CMID * HW];          // stage2 pre-BN
__device__ float g_stats[2 * CMID];                 // per-channel scale, shift
__device__ float g_wt1[576  * 256];                 // w1 k-major transposed, o-duplicated
__device__ float g_wt2[1152 * 256];                 // w2 k-major transposed, o-duplicated

// -------- weight transpose to k-major rows, duplicated along o --------
// wt[(k*C + c)*256 + 2*o + {0,1}] = w[(o*C + c)*9 + k]
__global__ void transpose_w_dup_kernel(const float* __restrict__ w,
                                       float* __restrict__ wt, int C) {
    int i = blockIdx.x * blockDim.x + threadIdx.x;   // over 9*C*128
    if (i < 9 * C * 128) {
        int o = i & 127;
        int r = i >> 7;              // r = k*C + c
        int k = r / C;
        int c = r - k * C;
        float v = w[(o * C + c) * 9 + k];
        wt[r * 256 + 2 * o]     = v;
        wt[r * 256 + 2 * o + 1] = v;
    }
}

// -------- 3x3 offset conv (pad 1). One thread = 4 consecutive w pixels. --------
template<int C>
__global__ void conv3x3_off_kernel(const float* __restrict__ x,
                                   const float* __restrict__ w,
                                   const float* __restrict__ bias,
                                   float* __restrict__ out)
{
    __shared__ float ws[C * 9];
    const int bo = blockIdx.y;         // b*18 + oc
    const int b  = bo / OFFC;
    const int oc = bo - b * OFFC;
    for (int i = threadIdx.x; i < C * 9; i += blockDim.x)
        ws[i] = w[oc * C * 9 + i];
    __syncthreads();

    const int quad = blockIdx.x * blockDim.x + threadIdx.x;   // 0..4095
    if (quad >= 4096) return;
    const int h  = quad >> 5;            // 32 quads per row
    const int w0 = (quad & 31) << 2;

    const float* xb = x + (size_t)b * C * HW;
    float acc0 = bias[oc], acc1 = acc0, acc2 = acc0, acc3 = acc0;

    for (int c = 0; c < C; c++) {
        const float* xc = xb + c * HW;
        float r[3][6];
        #pragma unroll
        for (int dy = 0; dy < 3; dy++) {
            int y = h - 1 + dy;
            bool yv = (y >= 0) && (y < HH);
            #pragma unroll
            for (int dx = 0; dx < 6; dx++) {
                int xx = w0 - 1 + dx;
                r[dy][dx] = (yv && xx >= 0 && xx < WW) ? xc[y * WW + xx] : 0.f;
            }
        }
        const float* wc = ws + c * 9;
        #pragma unroll
        for (int dy = 0; dy < 3; dy++) {
            #pragma unroll
            for (int kx = 0; kx < 3; kx++) {
                float wv = wc[dy * 3 + kx];
                acc0 += wv * r[dy][kx + 0];
                acc1 += wv * r[dy][kx + 1];
                acc2 += wv * r[dy][kx + 2];
                acc3 += wv * r[dy][kx + 3];
            }
        }
    }
    float4 v = make_float4(acc0, acc1, acc2, acc3);
    *reinterpret_cast<float4*>(&out[((size_t)bo) * HW + h * WW + w0]) = v;
}

// -------- fused deformable conv as implicit GEMM (f32x2 packed) --------
// Block: 128 output channels x 128 pixels (one image row). 256 threads.
// Thread micro-tile: 8 o x 8 px = 32 packed f32x2 accumulators.
// Bilinear meta (tap indices + validity-folded weights) precomputed once/block.
template<int C>
__global__ void __launch_bounds__(256, 2)
deform_kernel(const float* __restrict__ x,
              const float* __restrict__ offset,
              const float* __restrict__ wtd,    // [9*C][256] duplicated
              const float* __restrict__ bias,
              float* __restrict__ out)
{
    __shared__ ushort4 Mi[9][128];                  // clamped tap indices
    __shared__ float4  Mw[9][128];                  // validity-folded weights
    __shared__ __align__(16) float Wd[8][256];      // 8 rows, o-duplicated
    __shared__ __align__(16) float Ss[8][128];      // 8 rows of samples

    const int b     = blockIdx.y;
    const int pbase = blockIdx.x * 128;             // one full image row
    const int t  = threadIdx.x;
    const int pg = t & 15, og = t >> 4;
    const int p0 = pg * 8, o0 = og * 8;
    const int pl = t & 127, cq = t >> 7;

    const float* xb   = x + (size_t)b * C * HW;
    const float* offb = offset + (size_t)b * OFFC * HW;

    // ---- precompute bilinear metadata: 9 k x 128 px ----
    const int h = pbase >> 7;
    for (int i = t; i < 9 * 128; i += 256) {
        int k = i >> 7, wpx = i & 127;
        int pixel = pbase + wpx;
        float offy = offb[(2 * k) * HW + pixel];
        float offx = offb[(2 * k + 1) * HW + pixel];
        float py = (float)(h - 1 + k / 3) + offy;
        float px = (float)(wpx - 1 + (k - (k / 3) * 3)) + offx;
        float fy = floorf(py), fx = floorf(px);
        int y0 = (int)fy, x0 = (int)fx;
        float wy1 = py - fy, wx1 = px - fx;
        float wy0 = 1.f - wy1, wx0 = 1.f - wx1;
        bool y0v = ((unsigned)y0 < 128u);
        bool y1v = ((unsigned)(y0 + 1) < 128u);
        bool x0v = ((unsigned)x0 < 128u);
        bool x1v = ((unsigned)(x0 + 1) < 128u);
        int y0c = min(max(y0, 0), 127), y1c = min(max(y0 + 1, 0), 127);
        int x0c = min(max(x0, 0), 127), x1c = min(max(x0 + 1, 0), 127);
        Mw[k][wpx] = make_float4(y0v && x0v ? wy0 * wx0 : 0.f,
                                 y0v && x1v ? wy0 * wx1 : 0.f,
                                 y1v && x0v ? wy1 * wx0 : 0.f,
                                 y1v && x1v ? wy1 * wx1 : 0.f);
        Mi[k][wpx] = make_ushort4((unsigned short)(y0c * 128 + x0c),
                                  (unsigned short)(y0c * 128 + x1c),
                                  (unsigned short)(y1c * 128 + x0c),
                                  (unsigned short)(y1c * 128 + x1c));
    }
    __syncthreads();

    ull acc[8][4];
    #pragma unroll
    for (int i = 0; i < 8; i++)
        #pragma unroll
        for (int j = 0; j < 4; j++) acc[i][j] = 0ull;

    for (int k = 0; k < 9; k++) {
        #pragma unroll 1
        for (int c0 = 0; c0 < C; c0 += 8) {
            __syncthreads();   // previous GEMM done reading Wd/Ss
            // load 8 weight rows (duplicated): 2048 floats, 2 float4/thread
            {
                const float4* src = reinterpret_cast<const float4*>(
                    wtd + ((size_t)(k * C + c0)) * 256);
                float4* dst = reinterpret_cast<float4*>(&Wd[0][0]);
                dst[t]       = src[t];
                dst[t + 256] = src[t + 256];
            }
            // sampling: thread covers 4 channels at its pixel
            {
                ushort4 mi = Mi[k][pl];
                float4  mw = Mw[k][pl];
                const float* xc = xb + (size_t)(c0 + cq * 4) * HW;
                #pragma unroll
                for (int i = 0; i < 4; i++) {
                    const float* p = xc + (size_t)i * HW;
                    Ss[cq * 4 + i][pl] = mw.x * p[mi.x] + mw.y * p[mi.y]
                                       + mw.z * p[mi.z] + mw.w * p[mi.w];
                }
            }
            __syncthreads();
            // GEMM: 8 rows x (8 o x 4 px-pairs) packed FMA
            #pragma unroll
            for (int kc = 0; kc < 8; kc++) {
                ulonglong2 s01 = *reinterpret_cast<const ulonglong2*>(&Ss[kc][p0]);
                ulonglong2 s23 = *reinterpret_cast<const ulonglong2*>(&Ss[kc][p0 + 4]);
                const ulonglong2* wp =
                    reinterpret_cast<const ulonglong2*>(&Wd[kc][o0 * 2]);
                ulonglong2 wA = wp[0], wB = wp[1], wC2 = wp[2], wD = wp[3];
                ull sv[4] = {s01.x, s01.y, s23.x, s23.y};
                ull wv[8] = {wA.x, wA.y, wB.x, wB.y, wC2.x, wC2.y, wD.x, wD.y};
                #pragma unroll
                for (int i = 0; i < 8; i++)
                    #pragma unroll
                    for (int j = 0; j < 4; j++)
                        fma2(acc[i][j], wv[i], sv[j]);
            }
        }
    }

    // ---- epilogue: add bias, store ----
    float* ob = out + (size_t)b * 128 * HW + pbase;
    #pragma unroll
    for (int i = 0; i < 8; i++) {
        int o = o0 + i;
        ull bp;
        asm("mov.b64 %0, {%1, %1};" : "=l"(bp) : "r"(__float_as_uint(bias[o])));
        #pragma unroll
        for (int j = 0; j < 4; j++)
            asm("add.rn.f32x2 %0, %0, %1;" : "+l"(acc[i][j]) : "l"(bp));
        ulonglong2* dst = reinterpret_cast<ulonglong2*>(&ob[(size_t)o * HW + p0]);
        dst[0] = make_ulonglong2(acc[i][0], acc[i][1]);
        dst[1] = make_ulonglong2(acc[i][2], acc[i][3]);
    }
}

// -------- BN stats: one block per channel -> scale/shift --------
__global__ void bn_stats_kernel(const float* __restrict__ t,
                                const float* __restrict__ gamma,
                                const float* __restrict__ beta,
                                float* __restrict__ stats)
{
    const int c = blockIdx.x;
    float s = 0.f, s2 = 0.f;
    for (int b = 0; b < BATCH; b++) {
        const float* p = t + ((size_t)b * CMID + c) * HW;
        for (int i = threadIdx.x; i < HW; i += blockDim.x) {
            float v = p[i];
            s += v; s2 += v * v;
        }
    }
    __shared__ float sh[512], sh2[512];
    sh[threadIdx.x] = s; sh2[threadIdx.x] = s2;
    __syncthreads();
    for (int st = 256; st > 0; st >>= 1) {
        if (threadIdx.x < st) {
            sh[threadIdx.x]  += sh[threadIdx.x + st];
            sh2[threadIdx.x] += sh2[threadIdx.x + st];
        }
        __syncthreads();
    }
    if (threadIdx.x == 0) {
        const float n = (float)(BATCH * HW);
        float mean = sh[0] / n;
        float var  = sh2[0] / n - mean * mean;
        float inv  = rsqrtf(var + EPS);
        float sc   = gamma[c] * inv;
        stats[c]        = sc;
        stats[CMID + c] = beta[c] - mean * sc;
    }
}

// -------- BN apply + ReLU (vectorized) --------
__global__ void bn_apply_kernel(const float* __restrict__ in,
                                const float* __restrict__ stats,
                                float* __restrict__ out)
{
    const int total4 = BATCH * CMID * HW / 4;
    int i = blockIdx.x * blockDim.x + threadIdx.x;
    if (i >= total4) return;
    int e = i * 4;
    int c = (e >> 14) & 127;             // HW = 16384 per (b,c) slab
    float sc = stats[c], sh = stats[CMID + c];
    float4 v = reinterpret_cast<const float4*>(in)[i];
    v.x = fmaxf(v.x * sc + sh, 0.f);
    v.y = fmaxf(v.y * sc + sh, 0.f);
    v.z = fmaxf(v.z * sc + sh, 0.f);
    v.w = fmaxf(v.w * sc + sh, 0.f);
    reinterpret_cast<float4*>(out)[i] = v;
}

extern "C" void kernel_launch(void* const* d_in, const int* in_sizes, int n_in,
                              void* d_out, int out_size)
{
    const float* x      = (const float*)d_in[0];
    const float* w_off1 = (const float*)d_in[1];
    const float* b_off1 = (const float*)d_in[2];
    const float* w1     = (const float*)d_in[3];
    const float* b1     = (const float*)d_in[4];
    const float* g1     = (const float*)d_in[5];
    const float* be1    = (const float*)d_in[6];
    const float* w_off2 = (const float*)d_in[7];
    const float* b_off2 = (const float*)d_in[8];
    const float* w2     = (const float*)d_in[9];
    const float* b2     = (const float*)d_in[10];
    const float* g2     = (const float*)d_in[11];
    const float* be2    = (const float*)d_in[12];
    float* out = (float*)d_out;

    float *off, *t1, *t2, *stats, *wt1, *wt2;
    cudaGetSymbolAddress((void**)&off,   g_off);
    cudaGetSymbolAddress((void**)&t1,    g_t1);
    cudaGetSymbolAddress((void**)&t2,    g_t2);
    cudaGetSymbolAddress((void**)&stats, g_stats);
    cudaGetSymbolAddress((void**)&wt1,   g_wt1);
    cudaGetSymbolAddress((void**)&wt2,   g_wt2);

    // weight transposes (k-major, o-duplicated for f32x2 operands)
    transpose_w_dup_kernel<<<(9 * 64 * 128 + 255) / 256, 256>>>(w1, wt1, 64);
    transpose_w_dup_kernel<<<(9 * 128 * 128 + 255) / 256, 256>>>(w2, wt2, 128);

    // stage 1
    conv3x3_off_kernel<64><<<dim3(16, BATCH * OFFC), 256>>>(x, w_off1, b_off1, off);
    deform_kernel<64><<<dim3(HW / 128, BATCH), 256>>>(x, off, wt1, b1, t1);
    bn_stats_kernel<<<CMID, 512>>>(t1, g1, be1, stats);
    bn_apply_kernel<<<(BATCH * CMID * HW / 4 + 255) / 256, 256>>>(t1, stats, t1);

    // stage 2
    conv3x3_off_kernel<128><<<dim3(16, BATCH * OFFC), 256>>>(t1, w_off2, b_off2, off);
    deform_kernel<128><<<dim3(HW / 128, BATCH), 256>>>(t1, off, wt2, b2, t2);
    bn_stats_kernel<<<CMID, 512>>>(t2, g2, be2, stats);
    bn_apply_kernel<<<(BATCH * CMID * HW / 4 + 255) / 256, 256>>>(t2, stats, out);
}

// round 5
// speedup vs baseline: 1.4495x; 1.4495x over previous
#include <cuda_runtime.h>
#include <cuda_bf16.h>
#include <math.h>
#include <stdint.h>

#define BATCH 4
#define HW 16384
#define HH 128
#define WW 128
#define OFFC 18
#define CMID 128
#define EPS 1e-5f

#define SWZ128(o) ((o) ^ (((o) >> 3) & 0x70))

__device__ __forceinline__ uint32_t smem_u32(const void* p) {
    uint32_t a;
    asm("{ .reg .u64 t; cvta.to.shared.u64 t, %1; cvt.u32.u64 %0, t; }" : "=r"(a) : "l"(p));
    return a;
}
__device__ __forceinline__ uint32_t lds_u32(uint32_t a) {
    uint32_t v;
    asm volatile("ld.shared.b32 %0, [%1];" : "=r"(v) : "r"(a));
    return v;
}
__device__ __forceinline__ void mma16816(float* d, const uint32_t* a, const uint32_t* b) {
    asm volatile(
        "mma.sync.aligned.m16n8k16.row.col.f32.bf16.bf16.f32 "
        "{%0,%1,%2,%3}, {%4,%5,%6,%7}, {%8,%9}, {%0,%1,%2,%3};"
        : "+f"(d[0]), "+f"(d[1]), "+f"(d[2]), "+f"(d[3])
        : "r"(a[0]), "r"(a[1]), "r"(a[2]), "r"(a[3]), "r"(b[0]), "r"(b[1]));
}

// ---------------- scratch (device globals) ----------------
__device__ float g_off[BATCH * OFFC * HW];
__device__ float g_t1 [BATCH * CMID * HW];
__device__ float g_t2 [BATCH * CMID * HW];
__device__ float g_stats[2 * CMID];
__device__ __nv_bfloat16 g_whi1[128 * 576];
__device__ __nv_bfloat16 g_wlo1[128 * 576];
__device__ __nv_bfloat16 g_whi2[128 * 1152];
__device__ __nv_bfloat16 g_wlo2[128 * 1152];

// w[o][c][k] -> whi/wlo[o][kk], kk = k*C + c (bf16 hi/lo split)
__global__ void prep_w_bf16(const float* __restrict__ w,
                            __nv_bfloat16* __restrict__ whi,
                            __nv_bfloat16* __restrict__ wlo, int C) {
    int CK = C * 9;
    int i = blockIdx.x * blockDim.x + threadIdx.x;
    if (i < 128 * CK) {
        int o = i / CK, kk = i - o * CK;
        int k = kk / C, c = kk - k * C;
        float v = w[(o * C + c) * 9 + k];
        __nv_bfloat16 h = __float2bfloat16(v);
        whi[i] = h;
        wlo[i] = __float2bfloat16(v - __bfloat162float(h));
    }
}

// ---------------- 3x3 offset conv (unchanged, passing) ----------------
template<int C>
__global__ void conv3x3_off_kernel(const float* __restrict__ x,
                                   const float* __restrict__ w,
                                   const float* __restrict__ bias,
                                   float* __restrict__ out)
{
    __shared__ float ws[C * 9];
    const int bo = blockIdx.y;
    const int b  = bo / OFFC;
    const int oc = bo - b * OFFC;
    for (int i = threadIdx.x; i < C * 9; i += blockDim.x)
        ws[i] = w[oc * C * 9 + i];
    __syncthreads();

    const int quad = blockIdx.x * blockDim.x + threadIdx.x;
    if (quad >= 4096) return;
    const int h  = quad >> 5;
    const int w0 = (quad & 31) << 2;

    const float* xb = x + (size_t)b * C * HW;
    float acc0 = bias[oc], acc1 = acc0, acc2 = acc0, acc3 = acc0;

    for (int c = 0; c < C; c++) {
        const float* xc = xb + c * HW;
        float r[3][6];
        #pragma unroll
        for (int dy = 0; dy < 3; dy++) {
            int y = h - 1 + dy;
            bool yv = (y >= 0) && (y < HH);
            #pragma unroll
            for (int dx = 0; dx < 6; dx++) {
                int xx = w0 - 1 + dx;
                r[dy][dx] = (yv && xx >= 0 && xx < WW) ? xc[y * WW + xx] : 0.f;
            }
        }
        const float* wc = ws + c * 9;
        #pragma unroll
        for (int dy = 0; dy < 3; dy++) {
            #pragma unroll
            for (int kx = 0; kx < 3; kx++) {
                float wv = wc[dy * 3 + kx];
                acc0 += wv * r[dy][kx + 0];
                acc1 += wv * r[dy][kx + 1];
                acc2 += wv * r[dy][kx + 2];
                acc3 += wv * r[dy][kx + 3];
            }
        }
    }
    float4 v = make_float4(acc0, acc1, acc2, acc3);
    *reinterpret_cast<float4*>(&out[((size_t)bo) * HW + h * WW + w0]) = v;
}

// ---------------- deformable conv: mma.sync bf16x3 implicit GEMM ----------------
// Block = (batch b, image row). D[m=128 px][n=128 o] in registers (8 warps, 2x4).
// K streamed in 64-chunks: A = bilinear samples (bf16 hi/lo), B = weights (hi/lo).
// SMEM tiles SW128-swizzled, 128B rows. 3 passes: AhBh + AhBl + AlBh.
#define TILE    16384
#define OFF_MI  (4 * TILE)                      // 65536: ushort4[9*128]
#define OFF_MW  (OFF_MI + 9 * 128 * 8)          // float4[9*128]
#define SMEM_TOTAL (OFF_MW + 9 * 128 * 16)      // 93184

template<int C>
__global__ void __launch_bounds__(256, 2)
deform_mma(const float* __restrict__ x, const float* __restrict__ offs,
           const __nv_bfloat16* __restrict__ whi, const __nv_bfloat16* __restrict__ wlo,
           const float* __restrict__ bias, float* __restrict__ out)
{
    constexpr int CK  = C * 9;
    constexpr int NCH = CK / 64;
    extern __shared__ __align__(1024) char smem[];
    const uint32_t sbase = smem_u32(smem);
    const int tid = threadIdx.x, wid = tid >> 5, l = tid & 31;
    const int b = blockIdx.y;
    const int pbase = blockIdx.x * 128;
    const int hrow = pbase >> 7;

    const float* xb   = x + (size_t)b * C * HW;
    const float* offb = offs + (size_t)b * OFFC * HW;

    ushort4* Mi = (ushort4*)(smem + OFF_MI);
    float4*  Mw = (float4*)(smem + OFF_MW);

    // bilinear metadata: 9 k x 128 px (once per block)
    for (int i = tid; i < 9 * 128; i += 256) {
        int k = i >> 7, wpx = i & 127;
        int pixel = pbase + wpx;
        float offy = offb[(2 * k) * HW + pixel];
        float offx = offb[(2 * k + 1) * HW + pixel];
        float py = (float)(hrow - 1 + k / 3) + offy;
        float px_ = (float)(wpx - 1 + (k - (k / 3) * 3)) + offx;
        float fy = floorf(py), fx = floorf(px_);
        int y0 = (int)fy, x0 = (int)fx;
        float wy1 = py - fy, wx1 = px_ - fx;
        float wy0 = 1.f - wy1, wx0 = 1.f - wx1;
        bool y0v = ((unsigned)y0 < 128u);
        bool y1v = ((unsigned)(y0 + 1) < 128u);
        bool x0v = ((unsigned)x0 < 128u);
        bool x1v = ((unsigned)(x0 + 1) < 128u);
        int y0c = min(max(y0, 0), 127), y1c = min(max(y0 + 1, 0), 127);
        int x0c = min(max(x0, 0), 127), x1c = min(max(x0 + 1, 0), 127);
        Mw[i] = make_float4(y0v && x0v ? wy0 * wx0 : 0.f,
                            y0v && x1v ? wy0 * wx1 : 0.f,
                            y1v && x0v ? wy1 * wx0 : 0.f,
                            y1v && x1v ? wy1 * wx1 : 0.f);
        Mi[i] = make_ushort4((unsigned short)(y0c * 128 + x0c),
                             (unsigned short)(y0c * 128 + x1c),
                             (unsigned short)(y1c * 128 + x0c),
                             (unsigned short)(y1c * 128 + x1c));
    }

    const int px = tid & 127;
    const int cg = tid >> 7;

    // warp tile: M 2x64, N 4x32
    const int mrow = (wid & 1) * 64;
    const int ncol = (wid >> 1) * 32;
    // precomputed swizzle helpers (x < 128: SWZ128(r*128+x) = r*128 + (x ^ ((r&7)<<4)))
    uint32_t ra[4], ra8[4], xa[4], xa8[4], rb[4], xb_[4];
    #pragma unroll
    for (int i = 0; i < 4; i++) {
        int r  = mrow + i * 16 + (l >> 2);
        int r8 = r + 8;
        ra[i]  = sbase + r * 128;  xa[i]  = (r & 7) << 4;
        ra8[i] = sbase + r8 * 128; xa8[i] = (r8 & 7) << 4;
        int n  = ncol + i * 8 + (l >> 2);
        rb[i]  = sbase + 2 * TILE + n * 128; xb_[i] = (n & 7) << 4;
    }
    const uint32_t klane = 4 * (l & 3);

    float acc[4][4][4];
    #pragma unroll
    for (int i = 0; i < 4; i++)
        #pragma unroll
        for (int j = 0; j < 4; j++)
            #pragma unroll
            for (int q = 0; q < 4; q++) acc[i][j][q] = 0.f;

    for (int ch = 0; ch < NCH; ++ch) {
        __syncthreads();   // previous compute done reading tiles
        // ---- B fill: 128 o-rows x 64 kk (hi at +2*TILE, lo at +3*TILE) ----
        {
            const int o = tid >> 1, half = tid & 1;
            const __nv_bfloat16* sh = whi + (size_t)o * CK + ch * 64 + half * 32;
            const __nv_bfloat16* sl = wlo + (size_t)o * CK + ch * 64 + half * 32;
            #pragma unroll
            for (int g = 0; g < 4; ++g) {
                uint4 vh = *(const uint4*)(sh + g * 8);
                uint4 vl = *(const uint4*)(sl + g * 8);
                int off = o * 128 + half * 64 + g * 16;
                *(uint4*)(smem + 2 * TILE + SWZ128(off)) = vh;
                *(uint4*)(smem + 3 * TILE + SWZ128(off)) = vl;
            }
        }
        // ---- A fill: bilinear samples (hi at 0, lo at +TILE) ----
        {
            int k, c0;
            if (C == 64) { k = ch; c0 = 0; }
            else         { k = ch >> 1; c0 = (ch & 1) * 64; }
            ushort4 mi = Mi[k * 128 + px];
            float4  mw = Mw[k * 128 + px];
            const float* xc = xb + (size_t)(c0 + cg * 32) * HW;
            #pragma unroll
            for (int g = 0; g < 4; ++g) {
                uint32_t hp[4], lp[4];
                #pragma unroll
                for (int j = 0; j < 4; ++j) {
                    const float* p0 = xc + (size_t)(g * 8 + 2 * j) * HW;
                    const float* p1 = p0 + HW;
                    float s0 = mw.x * p0[mi.x] + mw.y * p0[mi.y]
                             + mw.z * p0[mi.z] + mw.w * p0[mi.w];
                    float s1 = mw.x * p1[mi.x] + mw.y * p1[mi.y]
                             + mw.z * p1[mi.z] + mw.w * p1[mi.w];
                    __nv_bfloat16 h0 = __float2bfloat16(s0);
                    __nv_bfloat16 h1 = __float2bfloat16(s1);
                    float l0 = s0 - __bfloat162float(h0);
                    float l1 = s1 - __bfloat162float(h1);
                    __nv_bfloat162 hh = __halves2bfloat162(h0, h1);
                    __nv_bfloat162 ll = __halves2bfloat162(__float2bfloat16(l0),
                                                           __float2bfloat16(l1));
                    hp[j] = *(uint32_t*)&hh;
                    lp[j] = *(uint32_t*)&ll;
                }
                int off = px * 128 + cg * 64 + g * 16;
                *(uint4*)(smem +        SWZ128(off)) = make_uint4(hp[0], hp[1], hp[2], hp[3]);
                *(uint4*)(smem + TILE + SWZ128(off)) = make_uint4(lp[0], lp[1], lp[2], lp[3]);
            }
        }
        __syncthreads();
        // ---- compute: 4 ksteps of 16, passes AhBh, AhBl, AlBh ----
        #pragma unroll
        for (int ks = 0; ks < 4; ++ks) {
            const uint32_t kb  = ks * 32 + klane;
            const uint32_t kb2 = kb + 16;
            uint32_t a[4][4], bf[4][2];
            // Ah + Bh
            #pragma unroll
            for (int i = 0; i < 4; i++) {
                a[i][0] = lds_u32(ra[i]  + (kb  ^ xa[i]));
                a[i][1] = lds_u32(ra8[i] + (kb  ^ xa8[i]));
                a[i][2] = lds_u32(ra[i]  + (kb2 ^ xa[i]));
                a[i][3] = lds_u32(ra8[i] + (kb2 ^ xa8[i]));
            }
            #pragma unroll
            for (int j = 0; j < 4; j++) {
                bf[j][0] = lds_u32(rb[j] + (kb  ^ xb_[j]));
                bf[j][1] = lds_u32(rb[j] + (kb2 ^ xb_[j]));
            }
            #pragma unroll
            for (int i = 0; i < 4; i++)
                #pragma unroll
                for (int j = 0; j < 4; j++)
                    mma16816(acc[i][j], a[i], bf[j]);
            // Ah + Bl
            #pragma unroll
            for (int j = 0; j < 4; j++) {
                bf[j][0] = lds_u32(rb[j] + TILE + (kb  ^ xb_[j]));
                bf[j][1] = lds_u32(rb[j] + TILE + (kb2 ^ xb_[j]));
            }
            #pragma unroll
            for (int i = 0; i < 4; i++)
                #pragma unroll
                for (int j = 0; j < 4; j++)
                    mma16816(acc[i][j], a[i], bf[j]);
            // Al + Bh
            #pragma unroll
            for (int i = 0; i < 4; i++) {
                a[i][0] = lds_u32(ra[i]  + TILE + (kb  ^ xa[i]));
                a[i][1] = lds_u32(ra8[i] + TILE + (kb  ^ xa8[i]));
                a[i][2] = lds_u32(ra[i]  + TILE + (kb2 ^ xa[i]));
                a[i][3] = lds_u32(ra8[i] + TILE + (kb2 ^ xa8[i]));
            }
            #pragma unroll
            for (int j = 0; j < 4; j++) {
                bf[j][0] = lds_u32(rb[j] + (kb  ^ xb_[j]));
                bf[j][1] = lds_u32(rb[j] + (kb2 ^ xb_[j]));
            }
            #pragma unroll
            for (int i = 0; i < 4; i++)
                #pragma unroll
                for (int j = 0; j < 4; j++)
                    mma16816(acc[i][j], a[i], bf[j]);
        }
    }

    // ---- epilogue: D[m=px][n=o] -> out[b][o][pbase+m], add bias ----
    float* ob = out + (size_t)b * 128 * HW + pbase;
    const int m0 = mrow + (l >> 2);
    #pragma unroll
    for (int j = 0; j < 4; j++) {
        int n0 = ncol + j * 8 + 2 * (l & 3);
        float bi0 = __ldg(&bias[n0]), bi1 = __ldg(&bias[n0 + 1]);
        #pragma unroll
        for (int i = 0; i < 4; i++) {
            int m = m0 + i * 16;
            ob[(size_t)n0       * HW + m]     = acc[i][j][0] + bi0;
            ob[(size_t)(n0 + 1) * HW + m]     = acc[i][j][1] + bi1;
            ob[(size_t)n0       * HW + m + 8] = acc[i][j][2] + bi0;
            ob[(size_t)(n0 + 1) * HW + m + 8] = acc[i][j][3] + bi1;
        }
    }
}

// ---------------- BN stats + apply (unchanged, passing) ----------------
__global__ void bn_stats_kernel(const float* __restrict__ t,
                                const float* __restrict__ gamma,
                                const float* __restrict__ beta,
                                float* __restrict__ stats)
{
    const int c = blockIdx.x;
    float s = 0.f, s2 = 0.f;
    for (int b = 0; b < BATCH; b++) {
        const float* p = t + ((size_t)b * CMID + c) * HW;
        for (int i = threadIdx.x; i < HW; i += blockDim.x) {
            float v = p[i];
            s += v; s2 += v * v;
        }
    }
    __shared__ float sh[512], sh2[512];
    sh[threadIdx.x] = s; sh2[threadIdx.x] = s2;
    __syncthreads();
    for (int st = 256; st > 0; st >>= 1) {
        if (threadIdx.x < st) {
            sh[threadIdx.x]  += sh[threadIdx.x + st];
            sh2[threadIdx.x] += sh2[threadIdx.x + st];
        }
        __syncthreads();
    }
    if (threadIdx.x == 0) {
        const float n = (float)(BATCH * HW);
        float mean = sh[0] / n;
        float var  = sh2[0] / n - mean * mean;
        float inv  = rsqrtf(var + EPS);
        float sc   = gamma[c] * inv;
        stats[c]        = sc;
        stats[CMID + c] = beta[c] - mean * sc;
    }
}

__global__ void bn_apply_kernel(const float* __restrict__ in,
                                const float* __restrict__ stats,
                                float* __restrict__ out)
{
    const int total4 = BATCH * CMID * HW / 4;
    int i = blockIdx.x * blockDim.x + threadIdx.x;
    if (i >= total4) return;
    int e = i * 4;
    int c = (e >> 14) & 127;
    float sc = stats[c], sh = stats[CMID + c];
    float4 v = reinterpret_cast<const float4*>(in)[i];
    v.x = fmaxf(v.x * sc + sh, 0.f);
    v.y = fmaxf(v.y * sc + sh, 0.f);
    v.z = fmaxf(v.z * sc + sh, 0.f);
    v.w = fmaxf(v.w * sc + sh, 0.f);
    reinterpret_cast<float4*>(out)[i] = v;
}

extern "C" void kernel_launch(void* const* d_in, const int* in_sizes, int n_in,
                              void* d_out, int out_size)
{
    const float* x      = (const float*)d_in[0];
    const float* w_off1 = (const float*)d_in[1];
    const float* b_off1 = (const float*)d_in[2];
    const float* w1     = (const float*)d_in[3];
    const float* b1     = (const float*)d_in[4];
    const float* g1     = (const float*)d_in[5];
    const float* be1    = (const float*)d_in[6];
    const float* w_off2 = (const float*)d_in[7];
    const float* b_off2 = (const float*)d_in[8];
    const float* w2     = (const float*)d_in[9];
    const float* b2     = (const float*)d_in[10];
    const float* g2     = (const float*)d_in[11];
    const float* be2    = (const float*)d_in[12];
    float* out = (float*)d_out;

    float *off, *t1, *t2, *stats;
    __nv_bfloat16 *whi1, *wlo1, *whi2, *wlo2;
    cudaGetSymbolAddress((void**)&off,   g_off);
    cudaGetSymbolAddress((void**)&t1,    g_t1);
    cudaGetSymbolAddress((void**)&t2,    g_t2);
    cudaGetSymbolAddress((void**)&stats, g_stats);
    cudaGetSymbolAddress((void**)&whi1,  g_whi1);
    cudaGetSymbolAddress((void**)&wlo1,  g_wlo1);
    cudaGetSymbolAddress((void**)&whi2,  g_whi2);
    cudaGetSymbolAddress((void**)&wlo2,  g_wlo2);

    cudaFuncSetAttribute(deform_mma<64>,
                         cudaFuncAttributeMaxDynamicSharedMemorySize, SMEM_TOTAL);
    cudaFuncSetAttribute(deform_mma<128>,
                         cudaFuncAttributeMaxDynamicSharedMemorySize, SMEM_TOTAL);

    // weight prep (bf16 hi/lo, k-major kk)
    prep_w_bf16<<<(128 * 576 + 255) / 256, 256>>>(w1, whi1, wlo1, 64);
    prep_w_bf16<<<(128 * 1152 + 255) / 256, 256>>>(w2, whi2, wlo2, 128);

    // stage 1
    conv3x3_off_kernel<64><<<dim3(16, BATCH * OFFC), 256>>>(x, w_off1, b_off1, off);
    deform_mma<64><<<dim3(128, BATCH), 256, SMEM_TOTAL>>>(x, off, whi1, wlo1, b1, t1);
    bn_stats_kernel<<<CMID, 512>>>(t1, g1, be1, stats);
    bn_apply_kernel<<<(BATCH * CMID * HW / 4 + 255) / 256, 256>>>(t1, stats, t1);

    // stage 2
    conv3x3_off_kernel<128><<<dim3(16, BATCH * OFFC), 256>>>(t1, w_off2, b_off2, off);
    deform_mma<128><<<dim3(128, BATCH), 256, SMEM_TOTAL>>>(t1, off, whi2, wlo2, b2, t2);
    bn_stats_kernel<<<CMID, 512>>>(t2, g2, be2, stats);
    bn_apply_kernel<<<(BATCH * CMID * HW / 4 + 255) / 256, 256>>>(t2, stats, out);
}

// round 6
// speedup vs baseline: 1.8301x; 1.2625x over previous
#include <cuda_runtime.h>
#include <cuda_bf16.h>
#include <math.h>
#include <stdint.h>

#define BATCH 4
#define HW 16384
#define HH 128
#define WW 128
#define OFFC 18
#define CMID 128
#define EPS 1e-5f

#define SWZ64(o) ((o) ^ (((o) >> 3) & 0x30))

__device__ __forceinline__ uint32_t smem_u32(const void* p) {
    uint32_t a;
    asm("{ .reg .u64 t; cvta.to.shared.u64 t, %1; cvt.u32.u64 %0, t; }" : "=r"(a) : "l"(p));
    return a;
}
__device__ __forceinline__ void ldmx4(uint32_t* r, uint32_t addr) {
    asm volatile("ldmatrix.sync.aligned.m8n8.x4.shared.b16 {%0,%1,%2,%3}, [%4];"
                 : "=r"(r[0]), "=r"(r[1]), "=r"(r[2]), "=r"(r[3]) : "r"(addr));
}
__device__ __forceinline__ void mma16816(float* d, const uint32_t* a, const uint32_t* b) {
    asm volatile(
        "mma.sync.aligned.m16n8k16.row.col.f32.bf16.bf16.f32 "
        "{%0,%1,%2,%3}, {%4,%5,%6,%7}, {%8,%9}, {%0,%1,%2,%3};"
        : "+f"(d[0]), "+f"(d[1]), "+f"(d[2]), "+f"(d[3])
        : "r"(a[0]), "r"(a[1]), "r"(a[2]), "r"(a[3]), "r"(b[0]), "r"(b[1]));
}

// ---------------- scratch (device globals) ----------------
__device__ float g_off[BATCH * OFFC * HW];
__device__ float g_t1 [BATCH * CMID * HW];
__device__ float g_t2 [BATCH * CMID * HW];
__device__ float g_stats[2 * CMID];
__device__ __nv_bfloat16 g_whi1[128 * 576];
__device__ __nv_bfloat16 g_wlo1[128 * 576];
__device__ __nv_bfloat16 g_whi2[128 * 1152];
__device__ __nv_bfloat16 g_wlo2[128 * 1152];

// w[o][c][k] -> whi/wlo[o][kk], kk = k*C + c (bf16 hi/lo split)
__global__ void prep_w_bf16(const float* __restrict__ w,
                            __nv_bfloat16* __restrict__ whi,
                            __nv_bfloat16* __restrict__ wlo, int C) {
    int CK = C * 9;
    int i = blockIdx.x * blockDim.x + threadIdx.x;
    if (i < 128 * CK) {
        int o = i / CK, kk = i - o * CK;
        int k = kk / C, c = kk - k * C;
        float v = w[(o * C + c) * 9 + k];
        __nv_bfloat16 h = __float2bfloat16(v);
        whi[i] = h;
        wlo[i] = __float2bfloat16(v - __bfloat162float(h));
    }
}

// ---------------- 3x3 offset conv: 6 oc per block, x read once ----------------
template<int C>
__global__ void __launch_bounds__(256)
conv_off6(const float* __restrict__ x, const float* __restrict__ w,
          const float* __restrict__ bias, float* __restrict__ out)
{
    extern __shared__ float ws[];             // [6][C][9]
    const int b  = blockIdx.y;
    const int g  = blockIdx.z;                // oc group: oc = g*6 + og
    for (int i = threadIdx.x; i < 6 * C * 9; i += 256)
        ws[i] = w[g * 6 * C * 9 + i];
    __syncthreads();

    const int quad = blockIdx.x * 256 + threadIdx.x;   // 4096 quads / 16 blocks
    const int h  = quad >> 5;
    const int w0 = (quad & 31) << 2;

    const float* xb = x + (size_t)b * C * HW;
    float acc[6][4];
    #pragma unroll
    for (int oc = 0; oc < 6; oc++) {
        float bv = bias[g * 6 + oc];
        acc[oc][0] = bv; acc[oc][1] = bv; acc[oc][2] = bv; acc[oc][3] = bv;
    }

    for (int c = 0; c < C; c++) {
        const float* xc = xb + c * HW;
        float r[3][6];
        #pragma unroll
        for (int dy = 0; dy < 3; dy++) {
            int y = h - 1 + dy;
            bool yv = (y >= 0) && (y < HH);
            #pragma unroll
            for (int dx = 0; dx < 6; dx++) {
                int xx = w0 - 1 + dx;
                r[dy][dx] = (yv && xx >= 0 && xx < WW) ? xc[y * WW + xx] : 0.f;
            }
        }
        #pragma unroll
        for (int oc = 0; oc < 6; oc++) {
            const float* wc = ws + (oc * C + c) * 9;
            #pragma unroll
            for (int dy = 0; dy < 3; dy++) {
                #pragma unroll
                for (int kx = 0; kx < 3; kx++) {
                    float wv = wc[dy * 3 + kx];
                    acc[oc][0] += wv * r[dy][kx + 0];
                    acc[oc][1] += wv * r[dy][kx + 1];
                    acc[oc][2] += wv * r[dy][kx + 2];
                    acc[oc][3] += wv * r[dy][kx + 3];
                }
            }
        }
    }
    #pragma unroll
    for (int oc = 0; oc < 6; oc++) {
        float4 v = make_float4(acc[oc][0], acc[oc][1], acc[oc][2], acc[oc][3]);
        *reinterpret_cast<float4*>(
            &out[((size_t)b * OFFC + g * 6 + oc) * HW + h * WW + w0]) = v;
    }
}

// ---------------- deformable conv: pipelined mma.sync bf16x3 ----------------
// Block = (b, image row). D[128 px][128 o]. K streamed in 32-chunks,
// double-buffered; fill(ch+1) overlaps compute(ch); one sync per chunk.
// Tiles: 64B rows (32 bf16), SW64 swizzle; fragments via ldmatrix.x4.
#define TILE32  8192
#define BUFSZ   (4 * TILE32)                   // Ahi, Alo, Bhi, Blo
#define OFF_MI  (2 * BUFSZ)                    // 65536
#define OFF_MW  (OFF_MI + 9 * 128 * 8)         // 74752
#define SMEM_TOTAL (OFF_MW + 9 * 128 * 16)     // 93184

template<int C>
__global__ void __launch_bounds__(256, 2)
deform_mma(const float* __restrict__ x, const float* __restrict__ offs,
           const __nv_bfloat16* __restrict__ whi, const __nv_bfloat16* __restrict__ wlo,
           const float* __restrict__ bias, float* __restrict__ out)
{
    constexpr int CK  = C * 9;
    constexpr int NCH = CK / 32;
    extern __shared__ __align__(1024) char smem[];
    const uint32_t sbase = smem_u32(smem);
    const int tid = threadIdx.x, wid = tid >> 5, l = tid & 31;
    const int b = blockIdx.y;
    const int pbase = blockIdx.x * 128;
    const int hrow = pbase >> 7;

    const float* xb   = x + (size_t)b * C * HW;
    const float* offb = offs + (size_t)b * OFFC * HW;

    ushort4* Mi = (ushort4*)(smem + OFF_MI);
    float4*  Mw = (float4*)(smem + OFF_MW);

    // bilinear metadata: 9 k x 128 px (once per block)
    for (int i = tid; i < 9 * 128; i += 256) {
        int k = i >> 7, wpx = i & 127;
        int pixel = pbase + wpx;
        float offy = offb[(2 * k) * HW + pixel];
        float offx = offb[(2 * k + 1) * HW + pixel];
        float py = (float)(hrow - 1 + k / 3) + offy;
        float px_ = (float)(wpx - 1 + (k - (k / 3) * 3)) + offx;
        float fy = floorf(py), fx = floorf(px_);
        int y0 = (int)fy, x0 = (int)fx;
        float wy1 = py - fy, wx1 = px_ - fx;
        float wy0 = 1.f - wy1, wx0 = 1.f - wx1;
        bool y0v = ((unsigned)y0 < 128u);
        bool y1v = ((unsigned)(y0 + 1) < 128u);
        bool x0v = ((unsigned)x0 < 128u);
        bool x1v = ((unsigned)(x0 + 1) < 128u);
        int y0c = min(max(y0, 0), 127), y1c = min(max(y0 + 1, 0), 127);
        int x0c = min(max(x0, 0), 127), x1c = min(max(x0 + 1, 0), 127);
        Mw[i] = make_float4(y0v && x0v ? wy0 * wx0 : 0.f,
                            y0v && x1v ? wy0 * wx1 : 0.f,
                            y1v && x0v ? wy1 * wx0 : 0.f,
                            y1v && x1v ? wy1 * wx1 : 0.f);
        Mi[i] = make_ushort4((unsigned short)(y0c * 128 + x0c),
                             (unsigned short)(y0c * 128 + x1c),
                             (unsigned short)(y1c * 128 + x0c),
                             (unsigned short)(y1c * 128 + x1c));
    }
    __syncthreads();

    const int px = tid & 127;
    const int cg = tid >> 7;                 // 0/1: 16 channels each of the 32-chunk

    // warp tile: M 2x64, N 4x32
    const int mrow = (wid & 1) * 64;
    const int ncol = (wid >> 1) * 32;

    // ldmatrix lane addressing (64B rows, SW64)
    // A x4: lanes 0-15 -> rows m..m+15 @ kb, 16-31 -> same rows @ kb+16
    uint32_t a_base[4], a_xm[4];
    {
        int row = mrow + (l & 15);
        #pragma unroll
        for (int i = 0; i < 4; i++) {
            int r = row + i * 16;
            a_base[i] = r * 64;
            a_xm[i]   = ((r >> 1) & 3) << 4;
        }
    }
    const uint32_t a_k = (l >> 4) * 16;
    // B x4: mat0 rows n..n+7 @kb, mat1 same @kb+16, mat2 rows n+8..n+15 @kb, mat3 @kb+16
    uint32_t b_base[2], b_xm[2];
    {
        int row = ncol + (l & 7) + ((l >> 4) & 1) * 8;
        #pragma unroll
        for (int jp = 0; jp < 2; jp++) {
            int r = row + jp * 16;
            b_base[jp] = r * 64;
            b_xm[jp]   = ((r >> 1) & 3) << 4;
        }
    }
    const uint32_t b_k = ((l >> 3) & 1) * 16;

    float acc[4][4][4];
    #pragma unroll
    for (int i = 0; i < 4; i++)
        #pragma unroll
        for (int j = 0; j < 4; j++)
            #pragma unroll
            for (int q = 0; q < 4; q++) acc[i][j][q] = 0.f;

    // ---- fill: chunk ch -> buffer ch&1 ----
    auto fill = [&](int ch) {
        char* tb = smem + (ch & 1) * BUFSZ;
        // B: 128 o-rows x 32 kk
        {
            const int o = tid >> 1, half = tid & 1;
            const uint4* sh = (const uint4*)(whi + (size_t)o * CK + ch * 32 + half * 16);
            const uint4* sl = (const uint4*)(wlo + (size_t)o * CK + ch * 32 + half * 16);
            uint4 h0 = sh[0], h1 = sh[1];
            uint4 l0 = sl[0], l1 = sl[1];
            int off = o * 64 + half * 32;
            *(uint4*)(tb + 2 * TILE32 + SWZ64(off))      = h0;
            *(uint4*)(tb + 2 * TILE32 + SWZ64(off + 16)) = h1;
            *(uint4*)(tb + 3 * TILE32 + SWZ64(off))      = l0;
            *(uint4*)(tb + 3 * TILE32 + SWZ64(off + 16)) = l1;
        }
        // A: bilinear samples, 16 channels per thread
        {
            int k, c0;
            if (C == 64) { k = ch >> 1; c0 = (ch & 1) * 32; }
            else         { k = ch >> 2; c0 = (ch & 3) * 32; }
            ushort4 mi = Mi[k * 128 + px];
            float4  mw = Mw[k * 128 + px];
            const float* xc = xb + (size_t)(c0 + cg * 16) * HW;
            uint32_t hp[8], lp[8];
            #pragma unroll
            for (int j = 0; j < 8; ++j) {
                const float* p0 = xc + (size_t)(2 * j) * HW;
                const float* p1 = p0 + HW;
                float s0 = mw.x * p0[mi.x] + mw.y * p0[mi.y]
                         + mw.z * p0[mi.z] + mw.w * p0[mi.w];
                float s1 = mw.x * p1[mi.x] + mw.y * p1[mi.y]
                         + mw.z * p1[mi.z] + mw.w * p1[mi.w];
                __nv_bfloat16 h0 = __float2bfloat16(s0);
                __nv_bfloat16 h1 = __float2bfloat16(s1);
                float e0 = s0 - __bfloat162float(h0);
                float e1 = s1 - __bfloat162float(h1);
                __nv_bfloat162 hh = __halves2bfloat162(h0, h1);
                __nv_bfloat162 ll = __halves2bfloat162(__float2bfloat16(e0),
                                                       __float2bfloat16(e1));
                hp[j] = *(uint32_t*)&hh;
                lp[j] = *(uint32_t*)&ll;
            }
            int off = px * 64 + cg * 32;
            *(uint4*)(tb + SWZ64(off))                = make_uint4(hp[0], hp[1], hp[2], hp[3]);
            *(uint4*)(tb + SWZ64(off + 16))           = make_uint4(hp[4], hp[5], hp[6], hp[7]);
            *(uint4*)(tb + TILE32 + SWZ64(off))       = make_uint4(lp[0], lp[1], lp[2], lp[3]);
            *(uint4*)(tb + TILE32 + SWZ64(off + 16))  = make_uint4(lp[4], lp[5], lp[6], lp[7]);
        }
    };

    fill(0);
    __syncthreads();

    for (int ch = 0; ch < NCH; ++ch) {
        if (ch + 1 < NCH) fill(ch + 1);
        // ---- compute(ch): buffer ch&1, 2 ksteps, passes AhBh/AhBl/AlBh ----
        const uint32_t tb = sbase + (ch & 1) * BUFSZ;
        const uint32_t Ahi = tb, Alo = tb + TILE32;
        const uint32_t Bhi = tb + 2 * TILE32, Blo = tb + 3 * TILE32;
        #pragma unroll
        for (int ks = 0; ks < 2; ++ks) {
            const uint32_t ak = ks * 32 + a_k;
            const uint32_t bk = ks * 32 + b_k;
            uint32_t af[4][4], bf[2][4];
            #pragma unroll
            for (int i = 0; i < 4; i++)
                ldmx4(af[i], Ahi + a_base[i] + (ak ^ a_xm[i]));
            #pragma unroll
            for (int jp = 0; jp < 2; jp++)
                ldmx4(bf[jp], Bhi + b_base[jp] + (bk ^ b_xm[jp]));
            #pragma unroll
            for (int i = 0; i < 4; i++)
                #pragma unroll
                for (int jp = 0; jp < 2; jp++) {
                    mma16816(acc[i][jp * 2],     af[i], &bf[jp][0]);
                    mma16816(acc[i][jp * 2 + 1], af[i], &bf[jp][2]);
                }
            #pragma unroll
            for (int jp = 0; jp < 2; jp++)
                ldmx4(bf[jp], Blo + b_base[jp] + (bk ^ b_xm[jp]));
            #pragma unroll
            for (int i = 0; i < 4; i++)
                #pragma unroll
                for (int jp = 0; jp < 2; jp++) {
                    mma16816(acc[i][jp * 2],     af[i], &bf[jp][0]);
                    mma16816(acc[i][jp * 2 + 1], af[i], &bf[jp][2]);
                }
            #pragma unroll
            for (int i = 0; i < 4; i++)
                ldmx4(af[i], Alo + a_base[i] + (ak ^ a_xm[i]));
            #pragma unroll
            for (int jp = 0; jp < 2; jp++)
                ldmx4(bf[jp], Bhi + b_base[jp] + (bk ^ b_xm[jp]));
            #pragma unroll
            for (int i = 0; i < 4; i++)
                #pragma unroll
                for (int jp = 0; jp < 2; jp++) {
                    mma16816(acc[i][jp * 2],     af[i], &bf[jp][0]);
                    mma16816(acc[i][jp * 2 + 1], af[i], &bf[jp][2]);
                }
        }
        __syncthreads();
    }

    // ---- epilogue: D[m=px][n=o] -> out[b][o][pbase+m], add bias ----
    float* ob = out + (size_t)b * 128 * HW + pbase;
    const int m0 = mrow + (l >> 2);
    #pragma unroll
    for (int j = 0; j < 4; j++) {
        int n0 = ncol + j * 8 + 2 * (l & 3);
        float bi0 = __ldg(&bias[n0]), bi1 = __ldg(&bias[n0 + 1]);
        #pragma unroll
        for (int i = 0; i < 4; i++) {
            int m = m0 + i * 16;
            ob[(size_t)n0       * HW + m]     = acc[i][j][0] + bi0;
            ob[(size_t)(n0 + 1) * HW + m]     = acc[i][j][1] + bi1;
            ob[(size_t)n0       * HW + m + 8] = acc[i][j][2] + bi0;
            ob[(size_t)(n0 + 1) * HW + m + 8] = acc[i][j][3] + bi1;
        }
    }
}

// ---------------- BN stats + apply (unchanged, passing) ----------------
__global__ void bn_stats_kernel(const float* __restrict__ t,
                                const float* __restrict__ gamma,
                                const float* __restrict__ beta,
                                float* __restrict__ stats)
{
    const int c = blockIdx.x;
    float s = 0.f, s2 = 0.f;
    for (int b = 0; b < BATCH; b++) {
        const float* p = t + ((size_t)b * CMID + c) * HW;
        for (int i = threadIdx.x; i < HW; i += blockDim.x) {
            float v = p[i];
            s += v; s2 += v * v;
        }
    }
    __shared__ float sh[512], sh2[512];
    sh[threadIdx.x] = s; sh2[threadIdx.x] = s2;
    __syncthreads();
    for (int st = 256; st > 0; st >>= 1) {
        if (threadIdx.x < st) {
            sh[threadIdx.x]  += sh[threadIdx.x + st];
            sh2[threadIdx.x] += sh2[threadIdx.x + st];
        }
        __syncthreads();
    }
    if (threadIdx.x == 0) {
        const float n = (float)(BATCH * HW);
        float mean = sh[0] / n;
        float var  = sh2[0] / n - mean * mean;
        float inv  = rsqrtf(var + EPS);
        float sc   = gamma[c] * inv;
        stats[c]        = sc;
        stats[CMID + c] = beta[c] - mean * sc;
    }
}

__global__ void bn_apply_kernel(const float* __restrict__ in,
                                const float* __restrict__ stats,
                                float* __restrict__ out)
{
    const int total4 = BATCH * CMID * HW / 4;
    int i = blockIdx.x * blockDim.x + threadIdx.x;
    if (i >= total4) return;
    int e = i * 4;
    int c = (e >> 14) & 127;
    float sc = stats[c], sh = stats[CMID + c];
    float4 v = reinterpret_cast<const float4*>(in)[i];
    v.x = fmaxf(v.x * sc + sh, 0.f);
    v.y = fmaxf(v.y * sc + sh, 0.f);
    v.z = fmaxf(v.z * sc + sh, 0.f);
    v.w = fmaxf(v.w * sc + sh, 0.f);
    reinterpret_cast<float4*>(out)[i] = v;
}

extern "C" void kernel_launch(void* const* d_in, const int* in_sizes, int n_in,
                              void* d_out, int out_size)
{
    const float* x      = (const float*)d_in[0];
    const float* w_off1 = (const float*)d_in[1];
    const float* b_off1 = (const float*)d_in[2];
    const float* w1     = (const float*)d_in[3];
    const float* b1     = (const float*)d_in[4];
    const float* g1     = (const float*)d_in[5];
    const float* be1    = (const float*)d_in[6];
    const float* w_off2 = (const float*)d_in[7];
    const float* b_off2 = (const float*)d_in[8];
    const float* w2     = (const float*)d_in[9];
    const float* b2     = (const float*)d_in[10];
    const float* g2     = (const float*)d_in[11];
    const float* be2    = (const float*)d_in[12];
    float* out = (float*)d_out;

    float *off, *t1, *t2, *stats;
    __nv_bfloat16 *whi1, *wlo1, *whi2, *wlo2;
    cudaGetSymbolAddress((void**)&off,   g_off);
    cudaGetSymbolAddress((void**)&t1,    g_t1);
    cudaGetSymbolAddress((void**)&t2,    g_t2);
    cudaGetSymbolAddress((void**)&stats, g_stats);
    cudaGetSymbolAddress((void**)&whi1,  g_whi1);
    cudaGetSymbolAddress((void**)&wlo1,  g_wlo1);
    cudaGetSymbolAddress((void**)&whi2,  g_whi2);
    cudaGetSymbolAddress((void**)&wlo2,  g_wlo2);

    cudaFuncSetAttribute(deform_mma<64>,
                         cudaFuncAttributeMaxDynamicSharedMemorySize, SMEM_TOTAL);
    cudaFuncSetAttribute(deform_mma<128>,
                         cudaFuncAttributeMaxDynamicSharedMemorySize, SMEM_TOTAL);
    cudaFuncSetAttribute(conv_off6<64>,
                         cudaFuncAttributeMaxDynamicSharedMemorySize, 6 * 64 * 9 * 4);
    cudaFuncSetAttribute(conv_off6<128>,
                         cudaFuncAttributeMaxDynamicSharedMemorySize, 6 * 128 * 9 * 4);

    // weight prep (bf16 hi/lo, k-major kk)
    prep_w_bf16<<<(128 * 576 + 255) / 256, 256>>>(w1, whi1, wlo1, 64);
    prep_w_bf16<<<(128 * 1152 + 255) / 256, 256>>>(w2, whi2, wlo2, 128);

    // stage 1
    conv_off6<64><<<dim3(16, BATCH, 3), 256, 6 * 64 * 9 * 4>>>(x, w_off1, b_off1, off);
    deform_mma<64><<<dim3(128, BATCH), 256, SMEM_TOTAL>>>(x, off, whi1, wlo1, b1, t1);
    bn_stats_kernel<<<CMID, 512>>>(t1, g1, be1, stats);
    bn_apply_kernel<<<(BATCH * CMID * HW / 4 + 255) / 256, 256>>>(t1, stats, t1);

    // stage 2
    conv_off6<128><<<dim3(16, BATCH, 3), 256, 6 * 128 * 9 * 4>>>(t1, w_off2, b_off2, off);
    deform_mma<128><<<dim3(128, BATCH), 256, SMEM_TOTAL>>>(t1, off, whi2, wlo2, b2, t2);
    bn_stats_kernel<<<CMID, 512>>>(t2, g2, be2, stats);
    bn_apply_kernel<<<(BATCH * CMID * HW / 4 + 255) / 256, 256>>>(t2, stats, out);
}

// round 7
// speedup vs baseline: 1.9060x; 1.0415x over previous
#include <cuda_runtime.h>
#include <cuda_bf16.h>
#include <math.h>
#include <stdint.h>

#define BATCH 4
#define HW 16384
#define HH 128
#define WW 128
#define OFFC 18
#define CMID 128
#define EPS 1e-5f

#define SWZ128(o) ((o) ^ (((o) >> 3) & 0x70))

__device__ __forceinline__ uint32_t smem_u32(const void* p) {
    uint32_t a;
    asm("{ .reg .u64 t; cvta.to.shared.u64 t, %1; cvt.u32.u64 %0, t; }" : "=r"(a) : "l"(p));
    return a;
}
__device__ __forceinline__ void ldmx4(uint32_t* r, uint32_t addr) {
    asm volatile("ldmatrix.sync.aligned.m8n8.x4.shared.b16 {%0,%1,%2,%3}, [%4];"
                 : "=r"(r[0]), "=r"(r[1]), "=r"(r[2]), "=r"(r[3]) : "r"(addr));
}
__device__ __forceinline__ void mma16816(float* d, const uint32_t* a, const uint32_t* b) {
    asm volatile(
        "mma.sync.aligned.m16n8k16.row.col.f32.bf16.bf16.f32 "
        "{%0,%1,%2,%3}, {%4,%5,%6,%7}, {%8,%9}, {%0,%1,%2,%3};"
        : "+f"(d[0]), "+f"(d[1]), "+f"(d[2]), "+f"(d[3])
        : "r"(a[0]), "r"(a[1]), "r"(a[2]), "r"(a[3]), "r"(b[0]), "r"(b[1]));
}

// ---------------- scratch (device globals) ----------------
__device__ float g_off[BATCH * OFFC * HW];
__device__ float g_t1 [BATCH * CMID * HW];
__device__ float g_t2 [BATCH * CMID * HW];
__device__ float g_stats[2 * CMID];
// pre-swizzled weight chunk images: [plane(hi/lo)][chunk][o:128][32 bf16]
__device__ __nv_bfloat16 g_wsw1[2 * 18 * 128 * 32];
__device__ __nv_bfloat16 g_wsw2[2 * 36 * 128 * 32];

// w[o][c][k] -> wsw[plane][ch][o][e], kk = ch*32+e = k*C + c
__global__ void prep_w_sw(const float* __restrict__ w,
                          __nv_bfloat16* __restrict__ wsw, int C) {
    const int CK = C * 9;
    const int NCH = CK / 32;
    int i = blockIdx.x * blockDim.x + threadIdx.x;     // over 2*CK*128
    if (i >= 2 * CK * 128) return;
    int plane = i / (CK * 128);
    int rem   = i - plane * CK * 128;
    int ch = rem / (128 * 32);
    int r2 = rem - ch * 128 * 32;
    int o  = r2 >> 5;
    int e  = r2 & 31;
    int kk = ch * 32 + e;
    int k = kk / C, c = kk - k * C;
    float v = w[(o * C + c) * 9 + k];
    __nv_bfloat16 h = __float2bfloat16(v);
    __nv_bfloat16 res = plane ? __float2bfloat16(v - __bfloat162float(h)) : h;
    wsw[((size_t)(plane * NCH + ch) * 128 + o) * 32 + e] = res;
}

// ---------------- 3x3 offset conv: 6 oc per block (unchanged, passing) ----------------
template<int C>
__global__ void __launch_bounds__(256)
conv_off6(const float* __restrict__ x, const float* __restrict__ w,
          const float* __restrict__ bias, float* __restrict__ out)
{
    extern __shared__ float ws[];             // [6][C][9]
    const int b  = blockIdx.y;
    const int g  = blockIdx.z;
    for (int i = threadIdx.x; i < 6 * C * 9; i += 256)
        ws[i] = w[g * 6 * C * 9 + i];
    __syncthreads();

    const int quad = blockIdx.x * 256 + threadIdx.x;
    const int h  = quad >> 5;
    const int w0 = (quad & 31) << 2;

    const float* xb = x + (size_t)b * C * HW;
    float acc[6][4];
    #pragma unroll
    for (int oc = 0; oc < 6; oc++) {
        float bv = bias[g * 6 + oc];
        acc[oc][0] = bv; acc[oc][1] = bv; acc[oc][2] = bv; acc[oc][3] = bv;
    }

    for (int c = 0; c < C; c++) {
        const float* xc = xb + c * HW;
        float r[3][6];
        #pragma unroll
        for (int dy = 0; dy < 3; dy++) {
            int y = h - 1 + dy;
            bool yv = (y >= 0) && (y < HH);
            #pragma unroll
            for (int dx = 0; dx < 6; dx++) {
                int xx = w0 - 1 + dx;
                r[dy][dx] = (yv && xx >= 0 && xx < WW) ? xc[y * WW + xx] : 0.f;
            }
        }
        #pragma unroll
        for (int oc = 0; oc < 6; oc++) {
            const float* wc = ws + (oc * C + c) * 9;
            #pragma unroll
            for (int dy = 0; dy < 3; dy++) {
                #pragma unroll
                for (int kx = 0; kx < 3; kx++) {
                    float wv = wc[dy * 3 + kx];
                    acc[oc][0] += wv * r[dy][kx + 0];
                    acc[oc][1] += wv * r[dy][kx + 1];
                    acc[oc][2] += wv * r[dy][kx + 2];
                    acc[oc][3] += wv * r[dy][kx + 3];
                }
            }
        }
    }
    #pragma unroll
    for (int oc = 0; oc < 6; oc++) {
        float4 v = make_float4(acc[oc][0], acc[oc][1], acc[oc][2], acc[oc][3]);
        *reinterpret_cast<float4*>(
            &out[((size_t)b * OFFC + g * 6 + oc) * HW + h * WW + w0]) = v;
    }
}

// ---------------- deformable conv: pipelined mma.sync bf16x3 (SW128) ----------------
// Tiles [128 rows][128B = 64 k-elems], SW128. k-chunk 32: the two 64B row-halves
// double-buffer (fill half (ch+1)&1 overlaps compute half ch&1). One sync/chunk.
#define OFF_AHI 0
#define OFF_ALO 16384
#define OFF_BHI 32768
#define OFF_BLO 49152
#define OFF_MI  65536
#define OFF_MW  (OFF_MI + 9 * 128 * 8)         // 74752
#define SMEM_TOTAL (OFF_MW + 9 * 128 * 16)     // 93184

template<int C>
__global__ void __launch_bounds__(256, 2)
deform_mma(const float* __restrict__ x, const float* __restrict__ offs,
           const __nv_bfloat16* __restrict__ wsw,
           const float* __restrict__ bias, float* __restrict__ out)
{
    constexpr int CK  = C * 9;
    constexpr int NCH = CK / 32;
    extern __shared__ __align__(1024) char smem[];
    const uint32_t sbase = smem_u32(smem);
    const int tid = threadIdx.x, wid = tid >> 5, l = tid & 31;
    const int b = blockIdx.y;
    const int pbase = blockIdx.x * 128;
    const int hrow = pbase >> 7;

    const float* xb   = x + (size_t)b * C * HW;
    const float* offb = offs + (size_t)b * OFFC * HW;

    ushort4* Mi = (ushort4*)(smem + OFF_MI);
    float4*  Mw = (float4*)(smem + OFF_MW);

    // bilinear metadata: 9 k x 128 px (once per block)
    for (int i = tid; i < 9 * 128; i += 256) {
        int k = i >> 7, wpx = i & 127;
        int pixel = pbase + wpx;
        float offy = offb[(2 * k) * HW + pixel];
        float offx = offb[(2 * k + 1) * HW + pixel];
        float py = (float)(hrow - 1 + k / 3) + offy;
        float px_ = (float)(wpx - 1 + (k - (k / 3) * 3)) + offx;
        float fy = floorf(py), fx = floorf(px_);
        int y0 = (int)fy, x0 = (int)fx;
        float wy1 = py - fy, wx1 = px_ - fx;
        float wy0 = 1.f - wy1, wx0 = 1.f - wx1;
        bool y0v = ((unsigned)y0 < 128u);
        bool y1v = ((unsigned)(y0 + 1) < 128u);
        bool x0v = ((unsigned)x0 < 128u);
        bool x1v = ((unsigned)(x0 + 1) < 128u);
        int y0c = min(max(y0, 0), 127), y1c = min(max(y0 + 1, 0), 127);
        int x0c = min(max(x0, 0), 127), x1c = min(max(x0 + 1, 0), 127);
        Mw[i] = make_float4(y0v && x0v ? wy0 * wx0 : 0.f,
                            y0v && x1v ? wy0 * wx1 : 0.f,
                            y1v && x0v ? wy1 * wx0 : 0.f,
                            y1v && x1v ? wy1 * wx1 : 0.f);
        Mi[i] = make_ushort4((unsigned short)(y0c * 128 + x0c),
                             (unsigned short)(y0c * 128 + x1c),
                             (unsigned short)(y1c * 128 + x0c),
                             (unsigned short)(y1c * 128 + x1c));
    }
    __syncthreads();

    const int px = tid & 127;
    const int cg = tid >> 7;                 // 0/1: 16 channels each of 32-chunk

    // warp tile: M 2x64, N 4x32
    const int mrow = (wid & 1) * 64;
    const int ncol = (wid >> 1) * 32;

    // ldmatrix lane addressing (128B rows, SW128)
    uint32_t a_base[4], a_x[4];
    {
        int row = mrow + (l & 15);
        #pragma unroll
        for (int i = 0; i < 4; i++) {
            int r = row + i * 16;
            a_base[i] = r * 128;
            a_x[i]    = (r & 7) << 4;
        }
    }
    const uint32_t a_k = (l >> 4) * 16;
    uint32_t b_base[2], b_x[2];
    {
        int row = ncol + (l & 7) + ((l >> 4) & 1) * 8;
        #pragma unroll
        for (int jp = 0; jp < 2; jp++) {
            int r = row + jp * 16;
            b_base[jp] = r * 128;
            b_x[jp]    = (r & 7) << 4;
        }
    }
    const uint32_t b_k = ((l >> 3) & 1) * 16;

    float acc[4][4][4];
    #pragma unroll
    for (int i = 0; i < 4; i++)
        #pragma unroll
        for (int j = 0; j < 4; j++)
            #pragma unroll
            for (int q = 0; q < 4; q++) acc[i][j][q] = 0.f;

    // ---- fill chunk ch into row-half ch&1 ----
    auto fill = [&](int ch) {
        const int h64 = (ch & 1) * 64;
        // B: coalesced copy of pre-swizzled chunk image (hi plane cg=0, lo cg=1)
        {
            const int o = tid & 127, plane = tid >> 7;
            const uint4* src = (const uint4*)(wsw +
                ((size_t)(plane * NCH + ch) * 128 + o) * 32);
            uint4 v0 = src[0], v1 = src[1], v2 = src[2], v3 = src[3];
            char* bt = smem + (plane ? OFF_BLO : OFF_BHI);
            int base = o * 128 + h64;
            *(uint4*)(bt + SWZ128(base))      = v0;
            *(uint4*)(bt + SWZ128(base + 16)) = v1;
            *(uint4*)(bt + SWZ128(base + 32)) = v2;
            *(uint4*)(bt + SWZ128(base + 48)) = v3;
        }
        // A: bilinear samples, 16 channels per thread
        {
            int k, c0;
            if (C == 64) { k = ch >> 1; c0 = (ch & 1) * 32; }
            else         { k = ch >> 2; c0 = (ch & 3) * 32; }
            ushort4 mi = Mi[k * 128 + px];
            float4  mw = Mw[k * 128 + px];
            const float* xc = xb + (size_t)(c0 + cg * 16) * HW;
            uint32_t hp[8], lp[8];
            #pragma unroll
            for (int g = 0; g < 4; ++g) {
                float s[4];
                #pragma unroll
                for (int cc = 0; cc < 4; ++cc) {
                    const float* p = xc + (size_t)(g * 4 + cc) * HW;
                    s[cc] = mw.x * p[mi.x] + mw.y * p[mi.y]
                          + mw.z * p[mi.z] + mw.w * p[mi.w];
                }
                #pragma unroll
                for (int q = 0; q < 2; ++q) {
                    float s0 = s[2 * q], s1 = s[2 * q + 1];
                    uint32_t hh;
                    asm("cvt.rn.bf16x2.f32 %0, %1, %2;" : "=r"(hh) : "f"(s1), "f"(s0));
                    float h0 = __uint_as_float(hh << 16);
                    float h1 = __uint_as_float(hh & 0xFFFF0000u);
                    float l0 = s0 - h0, l1 = s1 - h1;
                    uint32_t ll;
                    asm("cvt.rn.bf16x2.f32 %0, %1, %2;" : "=r"(ll) : "f"(l1), "f"(l0));
                    hp[g * 2 + q] = hh;
                    lp[g * 2 + q] = ll;
                }
            }
            int base = px * 128 + h64 + cg * 32;
            *(uint4*)(smem + OFF_AHI + SWZ128(base))      = make_uint4(hp[0], hp[1], hp[2], hp[3]);
            *(uint4*)(smem + OFF_AHI + SWZ128(base + 16)) = make_uint4(hp[4], hp[5], hp[6], hp[7]);
            *(uint4*)(smem + OFF_ALO + SWZ128(base))      = make_uint4(lp[0], lp[1], lp[2], lp[3]);
            *(uint4*)(smem + OFF_ALO + SWZ128(base + 16)) = make_uint4(lp[4], lp[5], lp[6], lp[7]);
        }
    };

    fill(0);
    __syncthreads();

    const uint32_t sAh = sbase + OFF_AHI, sAl = sbase + OFF_ALO;
    const uint32_t sBh = sbase + OFF_BHI, sBl = sbase + OFF_BLO;

    for (int ch = 0; ch < NCH; ++ch) {
        if (ch + 1 < NCH) fill(ch + 1);
        const uint32_t h64 = (ch & 1) * 64;
        #pragma unroll
        for (int ks = 0; ks < 2; ++ks) {
            const uint32_t ka = h64 + ks * 32 + a_k;
            const uint32_t kb = h64 + ks * 32 + b_k;
            uint32_t ah[4][4], al[4][4], bh[2][4], bl[2][4];
            #pragma unroll
            for (int i = 0; i < 4; i++)
                ldmx4(ah[i], sAh + a_base[i] + (ka ^ a_x[i]));
            #pragma unroll
            for (int jp = 0; jp < 2; jp++)
                ldmx4(bh[jp], sBh + b_base[jp] + (kb ^ b_x[jp]));
            #pragma unroll
            for (int i = 0; i < 4; i++)
                #pragma unroll
                for (int jp = 0; jp < 2; jp++) {
                    mma16816(acc[i][jp * 2],     ah[i], &bh[jp][0]);
                    mma16816(acc[i][jp * 2 + 1], ah[i], &bh[jp][2]);
                }
            #pragma unroll
            for (int jp = 0; jp < 2; jp++)
                ldmx4(bl[jp], sBl + b_base[jp] + (kb ^ b_x[jp]));
            #pragma unroll
            for (int i = 0; i < 4; i++)
                #pragma unroll
                for (int jp = 0; jp < 2; jp++) {
                    mma16816(acc[i][jp * 2],     ah[i], &bl[jp][0]);
                    mma16816(acc[i][jp * 2 + 1], ah[i], &bl[jp][2]);
                }
            #pragma unroll
            for (int i = 0; i < 4; i++)
                ldmx4(al[i], sAl + a_base[i] + (ka ^ a_x[i]));
            #pragma unroll
            for (int i = 0; i < 4; i++)
                #pragma unroll
                for (int jp = 0; jp < 2; jp++) {
                    mma16816(acc[i][jp * 2],     al[i], &bh[jp][0]);
                    mma16816(acc[i][jp * 2 + 1], al[i], &bh[jp][2]);
                }
        }
        __syncthreads();
    }

    // ---- epilogue: D[m=px][n=o] -> out[b][o][pbase+m], add bias ----
    float* ob = out + (size_t)b * 128 * HW + pbase;
    const int m0 = mrow + (l >> 2);
    #pragma unroll
    for (int j = 0; j < 4; j++) {
        int n0 = ncol + j * 8 + 2 * (l & 3);
        float bi0 = __ldg(&bias[n0]), bi1 = __ldg(&bias[n0 + 1]);
        #pragma unroll
        for (int i = 0; i < 4; i++) {
            int m = m0 + i * 16;
            ob[(size_t)n0       * HW + m]     = acc[i][j][0] + bi0;
            ob[(size_t)(n0 + 1) * HW + m]     = acc[i][j][1] + bi1;
            ob[(size_t)n0       * HW + m + 8] = acc[i][j][2] + bi0;
            ob[(size_t)(n0 + 1) * HW + m + 8] = acc[i][j][3] + bi1;
        }
    }
}

// ---------------- BN stats + apply (unchanged, passing) ----------------
__global__ void bn_stats_kernel(const float* __restrict__ t,
                                const float* __restrict__ gamma,
                                const float* __restrict__ beta,
                                float* __restrict__ stats)
{
    const int c = blockIdx.x;
    float s = 0.f, s2 = 0.f;
    for (int b = 0; b < BATCH; b++) {
        const float* p = t + ((size_t)b * CMID + c) * HW;
        for (int i = threadIdx.x; i < HW; i += blockDim.x) {
            float v = p[i];
            s += v; s2 += v * v;
        }
    }
    __shared__ float sh[512], sh2[512];
    sh[threadIdx.x] = s; sh2[threadIdx.x] = s2;
    __syncthreads();
    for (int st = 256; st > 0; st >>= 1) {
        if (threadIdx.x < st) {
            sh[threadIdx.x]  += sh[threadIdx.x + st];
            sh2[threadIdx.x] += sh2[threadIdx.x + st];
        }
        __syncthreads();
    }
    if (threadIdx.x == 0) {
        const float n = (float)(BATCH * HW);
        float mean = sh[0] / n;
        float var  = sh2[0] / n - mean * mean;
        float inv  = rsqrtf(var + EPS);
        float sc   = gamma[c] * inv;
        stats[c]        = sc;
        stats[CMID + c] = beta[c] - mean * sc;
    }
}

__global__ void bn_apply_kernel(const float* __restrict__ in,
                                const float* __restrict__ stats,
                                float* __restrict__ out)
{
    const int total4 = BATCH * CMID * HW / 4;
    int i = blockIdx.x * blockDim.x + threadIdx.x;
    if (i >= total4) return;
    int e = i * 4;
    int c = (e >> 14) & 127;
    float sc = stats[c], sh = stats[CMID + c];
    float4 v = reinterpret_cast<const float4*>(in)[i];
    v.x = fmaxf(v.x * sc + sh, 0.f);
    v.y = fmaxf(v.y * sc + sh, 0.f);
    v.z = fmaxf(v.z * sc + sh, 0.f);
    v.w = fmaxf(v.w * sc + sh, 0.f);
    reinterpret_cast<float4*>(out)[i] = v;
}

extern "C" void kernel_launch(void* const* d_in, const int* in_sizes, int n_in,
                              void* d_out, int out_size)
{
    const float* x      = (const float*)d_in[0];
    const float* w_off1 = (const float*)d_in[1];
    const float* b_off1 = (const float*)d_in[2];
    const float* w1     = (const float*)d_in[3];
    const float* b1     = (const float*)d_in[4];
    const float* g1     = (const float*)d_in[5];
    const float* be1    = (const float*)d_in[6];
    const float* w_off2 = (const float*)d_in[7];
    const float* b_off2 = (const float*)d_in[8];
    const float* w2     = (const float*)d_in[9];
    const float* b2     = (const float*)d_in[10];
    const float* g2     = (const float*)d_in[11];
    const float* be2    = (const float*)d_in[12];
    float* out = (float*)d_out;

    float *off, *t1, *t2, *stats;
    __nv_bfloat16 *wsw1, *wsw2;
    cudaGetSymbolAddress((void**)&off,   g_off);
    cudaGetSymbolAddress((void**)&t1,    g_t1);
    cudaGetSymbolAddress((void**)&t2,    g_t2);
    cudaGetSymbolAddress((void**)&stats, g_stats);
    cudaGetSymbolAddress((void**)&wsw1,  g_wsw1);
    cudaGetSymbolAddress((void**)&wsw2,  g_wsw2);

    cudaFuncSetAttribute(deform_mma<64>,
                         cudaFuncAttributeMaxDynamicSharedMemorySize, SMEM_TOTAL);
    cudaFuncSetAttribute(deform_mma<128>,
                         cudaFuncAttributeMaxDynamicSharedMemorySize, SMEM_TOTAL);
    cudaFuncSetAttribute(conv_off6<64>,
                         cudaFuncAttributeMaxDynamicSharedMemorySize, 6 * 64 * 9 * 4);
    cudaFuncSetAttribute(conv_off6<128>,
                         cudaFuncAttributeMaxDynamicSharedMemorySize, 6 * 128 * 9 * 4);

    // weight prep (bf16 hi/lo, pre-swizzled chunk images)
    prep_w_sw<<<(2 * 576 * 128 + 255) / 256, 256>>>(w1, wsw1, 64);
    prep_w_sw<<<(2 * 1152 * 128 + 255) / 256, 256>>>(w2, wsw2, 128);

    // stage 1
    conv_off6<64><<<dim3(16, BATCH, 3), 256, 6 * 64 * 9 * 4>>>(x, w_off1, b_off1, off);
    deform_mma<64><<<dim3(128, BATCH), 256, SMEM_TOTAL>>>(x, off, wsw1, b1, t1);
    bn_stats_kernel<<<CMID, 512>>>(t1, g1, be1, stats);
    bn_apply_kernel<<<(BATCH * CMID * HW / 4 + 255) / 256, 256>>>(t1, stats, t1);

    // stage 2
    conv_off6<128><<<dim3(16, BATCH, 3), 256, 6 * 128 * 9 * 4>>>(t1, w_off2, b_off2, off);
    deform_mma<128><<<dim3(128, BATCH), 256, SMEM_TOTAL>>>(t1, off, wsw2, b2, t2);
    bn_stats_kernel<<<CMID, 512>>>(t2, g2, be2, stats);
    bn_apply_kernel<<<(BATCH * CMID * HW / 4 + 255) / 256, 256>>>(t2, stats, out);
}